// round 5
// baseline (speedup 1.0000x reference)
#include <cuda_runtime.h>
#include <math.h>
#include <stdint.h>

#define BB 8
#define NN 2500
#define EE 100
#define FF 50
#define YY 8922
#define KK 9
#define BY (BB*YY)

#define HS 52          // g_h row stride (208B, 16B-aligned rows)
#define ATY 512        // labels per attn CTA (1 per thread)

typedef unsigned long long ull;

__device__ float g_h[BB*NN*HS];     // conv output h[b][n][f], padded rows
__device__ float g_loss[BY];        // per-(b,y) BCE terms

__device__ __forceinline__ void ffma2(ull &d, ull a, ull b) {
    asm("fma.rn.f32x2 %0, %1, %2, %0;" : "+l"(d) : "l"(a), "l"(b));
}
__device__ __forceinline__ ull pk2(float v) {
    ull r; unsigned u = __float_as_uint(v);
    asm("mov.b64 %0, {%1, %2};" : "=l"(r) : "r"(u), "r"(u));
    return r;
}
__device__ __forceinline__ float lo32(ull v){ return __uint_as_float((unsigned)v); }
__device__ __forceinline__ float hi32(ull v){ return __uint_as_float((unsigned)(v>>32)); }
__device__ __forceinline__ float sum2(ull v){ return lo32(v) + hi32(v); }

// ======================= Kernel 1: embed + conv1d(K=9,SAME) + tanh =======================
// grid (27, 8), 384 threads. thread = (tn in 0..95, eq in 0..3). 96-n tile.
#define CVN 96
__global__ __launch_bounds__(384, 1)
void conv_kernel(const int* __restrict__ x, const float* __restrict__ embW,
                 const float* __restrict__ convW, const float* __restrict__ convB) {
    extern __shared__ float sm[];
    float* emb = sm;                    // 104*101 = 10504
    float* wsm = emb + 104*101;         // 900*50 = 45000, wsm[(e*9+k)*50+f]
    int*  toks = (int*)(wsm + 45000);   // 104

    int b = blockIdx.y, base = blockIdx.x * CVN, tid = threadIdx.x;

    if (tid < CVN + 8) {
        int n = base - 4 + tid;
        toks[tid] = (n >= 0 && n < NN) ? x[b*NN + n] : -1;
    }
    __syncthreads();
    for (int j = tid; j < FF*EE*KK; j += 384) {
        int f = j / 900, r = j - f*900;
        wsm[r*FF + f] = convW[j];
    }
    for (int j = tid; j < (CVN+8)*EE; j += 384) {
        int row = j / EE, c = j - row*EE;
        int tk = toks[row];
        emb[row*101 + c] = (tk >= 0) ? embW[(size_t)tk*EE + c] : 0.f;
    }
    __syncthreads();

    int tn = tid % CVN;
    int eq = tid / CVN;

    ull acc[25];
    #pragma unroll
    for (int q = 0; q < 25; q++) acc[q] = 0ull;

    for (int ee = 0; ee < 25; ee++) {
        int e = eq*25 + ee;
        #pragma unroll
        for (int k = 0; k < KK; k++) {
            ull v = pk2(emb[(tn + k)*101 + e]);
            const ull* wr = (const ull*)&wsm[(e*KK + k)*FF];
            #pragma unroll
            for (int q = 0; q < 25; q++) ffma2(acc[q], wr[q], v);
        }
    }
    __syncthreads();
    float* part = sm;  // 3*96*50 = 14400 floats (aliased scratch)
    if (eq > 0) {
        float* p = part + (eq-1)*CVN*FF + tn*FF;
        #pragma unroll
        for (int q = 0; q < 25; q++) {
            p[2*q]   = lo32(acc[q]);
            p[2*q+1] = hi32(acc[q]);
        }
    }
    __syncthreads();
    if (eq == 0) {
        int n = base + tn;
        if (n < NN) {
            float* dst = &g_h[((size_t)b*NN + n)*HS];
            const float* p0 = part + tn*FF;
            const float* p1 = part + CVN*FF + tn*FF;
            const float* p2 = part + 2*CVN*FF + tn*FF;
            #pragma unroll
            for (int q = 0; q < 25; q++) {
                float a0 = lo32(acc[q]) + p0[2*q]   + p1[2*q]   + p2[2*q]   + convB[2*q];
                float a1 = hi32(acc[q]) + p0[2*q+1] + p1[2*q+1] + p2[2*q+1] + convB[2*q+1];
                dst[2*q]   = tanhf(a0);
                dst[2*q+1] = tanhf(a1);
            }
        }
    }
}

// ======================= Kernel 2: per-thread-label fused attention =======================
// grid (18, 8), 512 threads. thread t owns y = y0 + t; U row in registers.
// Pass1: e = exp(U.h_n), d += e, e -> alpha_out (coalesced via warp transpose tile).
// Pass2: a = e/d, m[50] += a*h_n (registers), a -> alpha_out. End: logit = F.m.
__global__ __launch_bounds__(ATY, 1)
void attn_kernel(const float* __restrict__ Uw, const float* __restrict__ finW,
                 const float* __restrict__ finB, const float* __restrict__ tgt,
                 float* __restrict__ yhat_out, float* __restrict__ alpha_out) {
    extern __shared__ float sm[];
    float* stage = sm;                   // ATY*52 = 26624 floats
    float* tiles = sm + ATY*52;          // 16 warps * 32*33 = 16896 floats

    int b = blockIdx.y, y0 = blockIdx.x*ATY, tid = threadIdx.x;
    int w = tid >> 5, lane = tid & 31;
    float* tile = tiles + w*(32*33);
    int y = y0 + tid;
    bool valid = (y < YY);
    int yc = valid ? y : (YY-1);
    const float* hb = g_h + (size_t)b*NN*HS;

    // ---- stage U coalesced, then pull own row into registers ----
    for (int j = tid; j < ATY*FF; j += ATY) {
        int r = j / FF, f = j - r*FF;
        int yy = y0 + r; if (yy >= YY) yy = YY-1;
        stage[r*52 + f] = Uw[(size_t)yy*FF + f];
    }
    __syncthreads();
    ull wreg[25];
    {
        const ull* src = (const ull*)(stage + tid*52);
        #pragma unroll
        for (int q = 0; q < 25; q++) wreg[q] = src[q];
    }

    // ---------------- Pass 1: e = exp(score), d accumulation ----------------
    float d = 0.f;
    for (int n0 = 0; n0 < NN; n0 += 32) {
        int w32 = (NN - n0 < 32) ? (NN - n0) : 32;
        for (int nl = 0; nl < w32; nl++) {
            const float* hrow = hb + (n0 + nl)*HS;
            const ulonglong2* hr = (const ulonglong2*)hrow;
            ull sa = 0ull, sb = 0ull;
            #pragma unroll
            for (int q = 0; q < 12; q++) {
                ulonglong2 hv = hr[q];
                ffma2(sa, wreg[2*q],   hv.x);
                ffma2(sb, wreg[2*q+1], hv.y);
            }
            ffma2(sa, wreg[24], *(const ull*)(hrow + 48));
            float s = sum2(sa) + sum2(sb);
            float e = __expf(s);
            d += e;
            tile[lane*33 + nl] = e;
        }
        __syncwarp();
        #pragma unroll 4
        for (int r = 0; r < 32; r++) {
            int yr = y0 + w*32 + r;
            if (yr < YY && lane < w32)
                alpha_out[(size_t)(b*YY + yr)*NN + n0 + lane] = tile[r*33 + lane];
        }
        __syncthreads();   // convoy warps: keep h L1-resident window small
    }
    float inv = 1.f / d;

    // ---------------- Pass 2: m += alpha*h; alpha written normalized ----------------
    #pragma unroll
    for (int q = 0; q < 25; q++) wreg[q] = 0ull;   // reuse as m accumulator
    for (int n0 = 0; n0 < NN; n0 += 32) {
        int w32 = (NN - n0 < 32) ? (NN - n0) : 32;
        #pragma unroll 4
        for (int r = 0; r < 32; r++) {
            int yr = y0 + w*32 + r; if (yr >= YY) yr = YY-1;
            if (lane < w32)
                tile[r*33 + lane] = alpha_out[(size_t)(b*YY + yr)*NN + n0 + lane];
        }
        __syncwarp();
        for (int nl = 0; nl < w32; nl++) {
            float e = tile[lane*33 + nl];
            float a = e * inv;
            tile[lane*33 + nl] = a;
            ull a2 = pk2(a);
            const float* hrow = hb + (n0 + nl)*HS;
            const ulonglong2* hr = (const ulonglong2*)hrow;
            #pragma unroll
            for (int q = 0; q < 12; q++) {
                ulonglong2 hv = hr[q];
                ffma2(wreg[2*q],   a2, hv.x);
                ffma2(wreg[2*q+1], a2, hv.y);
            }
            ffma2(wreg[24], a2, *(const ull*)(hrow + 48));
        }
        __syncwarp();
        #pragma unroll 4
        for (int r = 0; r < 32; r++) {
            int yr = y0 + w*32 + r;
            if (yr < YY && lane < w32)
                alpha_out[(size_t)(b*YY + yr)*NN + n0 + lane] = tile[r*33 + lane];
        }
        __syncthreads();
    }

    // ---- stage F, finish logits ----
    for (int j = tid; j < ATY*FF; j += ATY) {
        int r = j / FF, f = j - r*FF;
        int yy = y0 + r; if (yy >= YY) yy = YY-1;
        stage[r*52 + f] = finW[(size_t)yy*FF + f];
    }
    __syncthreads();
    ull acc = 0ull;
    {
        const ull* fr = (const ull*)(stage + tid*52);
        #pragma unroll
        for (int q = 0; q < 25; q++) ffma2(acc, wreg[q], fr[q]);
    }
    if (valid) {
        float logit = sum2(acc) + finB[y];
        float p = 1.f / (1.f + __expf(-logit));
        yhat_out[(size_t)b*YY + y] = p;
        float pc = fminf(fmaxf(p, 1e-7f), 1.f - 1e-7f);
        float t = tgt[(size_t)b*YY + y];
        g_loss[(size_t)b*YY + y] = -(t*logf(pc) + (1.f - t)*log1pf(-pc));
    }
}

// ======================= Kernel 3: deterministic loss reduction =======================
__global__ void loss_kernel(float* __restrict__ out) {
    __shared__ float r[1024];
    int tid = threadIdx.x;
    float a = 0.f;
    for (int i = tid; i < BY; i += 1024) a += g_loss[i];
    r[tid] = a;
    __syncthreads();
    for (int st = 512; st > 0; st >>= 1) {
        if (tid < st) r[tid] += r[tid + st];
        __syncthreads();
    }
    if (tid == 0) out[BY] = r[0] / (float)BY;
}

// ======================= Launch =======================
extern "C" void kernel_launch(void* const* d_in, const int* in_sizes, int n_in,
                              void* d_out, int out_size) {
    const int*   x      = (const int*)d_in[0];
    const float* target = (const float*)d_in[1];
    const float* embW   = (const float*)d_in[2];
    const float* convW  = (const float*)d_in[3];
    const float* convB  = (const float*)d_in[4];
    const float* Uw     = (const float*)d_in[5];
    const float* finW   = (const float*)d_in[6];
    const float* finB   = (const float*)d_in[7];
    float* out = (float*)d_out;
    float* yhat  = out;            // [B,Y]
    float* alpha = out + BY + 1;   // [B,Y,N]; out[BY] = loss

    const int conv_smem = (104*101 + 45000)*4 + 104*4;          // 222432
    const int attn_smem = (ATY*52 + 16*32*33)*4;                // 174080

    cudaFuncSetAttribute(conv_kernel, cudaFuncAttributeMaxDynamicSharedMemorySize, conv_smem);
    cudaFuncSetAttribute(attn_kernel, cudaFuncAttributeMaxDynamicSharedMemorySize, attn_smem);

    conv_kernel<<<dim3((NN + CVN - 1)/CVN, BB), 384, conv_smem>>>(x, embW, convW, convB);
    attn_kernel<<<dim3((YY + ATY - 1)/ATY, BB), ATY, attn_smem>>>(Uw, finW, finB, target, yhat, alpha);
    loss_kernel<<<1, 1024>>>(out);
}

// round 6
// speedup vs baseline: 2.2492x; 2.2492x over previous
#include <cuda_runtime.h>
#include <math.h>
#include <stdint.h>

#define BB 8
#define NN 2500
#define EE 100
#define FF 50
#define YY 8922
#define KK 9
#define BY (BB*YY)

#define HS   50        // g_h row stride in floats (unpadded; stride-50 LDS.64 is bank-conflict-free)
#define ATY  24        // y rows per attn CTA (2 groups x 12)
#define TR   12        // y rows per thread
#define TM   4         // n cols per thread
#define CN   512       // n rows per chunk
#define NCHK 5         // ceil(2500/512)
#define CHUNK_FLTS (CN*HS)   // 25600

typedef unsigned long long ull;

__device__ float g_h[BB*NN*HS];
__device__ float g_loss[BY];

__device__ __forceinline__ void ffma2(ull &d, ull a, ull b) {
    asm("fma.rn.f32x2 %0, %1, %2, %0;" : "+l"(d) : "l"(a), "l"(b));
}
__device__ __forceinline__ ull pk2(float v) {
    ull r; unsigned u = __float_as_uint(v);
    asm("mov.b64 %0, {%1, %2};" : "=l"(r) : "r"(u), "r"(u));
    return r;
}
__device__ __forceinline__ float lo32(ull v){ return __uint_as_float((unsigned)v); }
__device__ __forceinline__ float hi32(ull v){ return __uint_as_float((unsigned)(v>>32)); }
__device__ __forceinline__ float sum2(ull v){ return lo32(v) + hi32(v); }

__device__ __forceinline__ uint32_t s2u(const void* p) {
    return (uint32_t)__cvta_generic_to_shared(p);
}
__device__ __forceinline__ void mbar_init(uint32_t mbar, int cnt) {
    asm volatile("mbarrier.init.shared.b64 [%0], %1;" :: "r"(mbar), "r"(cnt) : "memory");
}
__device__ __forceinline__ void tma_bulk(uint32_t dst, const void* src, uint32_t bytes, uint32_t mbar) {
    asm volatile("mbarrier.arrive.expect_tx.shared.b64 _, [%0], %1;" :: "r"(mbar), "r"(bytes) : "memory");
    asm volatile("cp.async.bulk.shared::cta.global.mbarrier::complete_tx::bytes [%0], [%1], %2, [%3];"
                 :: "r"(dst), "l"(src), "r"(bytes), "r"(mbar) : "memory");
}
__device__ __forceinline__ void mbar_wait(uint32_t mbar, int parity) {
    uint32_t done;
    do {
        asm volatile("{\n\t.reg .pred p;\n\t"
                     "mbarrier.try_wait.parity.acquire.cta.shared::cta.b64 p, [%1], %2, 0x989680;\n\t"
                     "selp.b32 %0, 1, 0, p;\n\t}"
                     : "=r"(done) : "r"(mbar), "r"((uint32_t)parity) : "memory");
    } while (!done);
}

// ======================= Kernel 1: embed + conv1d(K=9,SAME) + tanh =======================
#define CVN 96
__global__ __launch_bounds__(384, 1)
void conv_kernel(const int* __restrict__ x, const float* __restrict__ embW,
                 const float* __restrict__ convW, const float* __restrict__ convB) {
    extern __shared__ float sm[];
    float* emb = sm;                    // 104*101
    float* wsm = emb + 104*101;         // 900*50
    int*  toks = (int*)(wsm + 45000);

    int b = blockIdx.y, base = blockIdx.x * CVN, tid = threadIdx.x;

    if (tid < CVN + 8) {
        int n = base - 4 + tid;
        toks[tid] = (n >= 0 && n < NN) ? x[b*NN + n] : -1;
    }
    __syncthreads();
    for (int j = tid; j < FF*EE*KK; j += 384) {
        int f = j / 900, r = j - f*900;
        wsm[r*FF + f] = convW[j];
    }
    for (int j = tid; j < (CVN+8)*EE; j += 384) {
        int row = j / EE, c = j - row*EE;
        int tk = toks[row];
        emb[row*101 + c] = (tk >= 0) ? embW[(size_t)tk*EE + c] : 0.f;
    }
    __syncthreads();

    int tn = tid % CVN;
    int eq = tid / CVN;

    ull acc[25];
    #pragma unroll
    for (int q = 0; q < 25; q++) acc[q] = 0ull;

    for (int ee = 0; ee < 25; ee++) {
        int e = eq*25 + ee;
        #pragma unroll
        for (int k = 0; k < KK; k++) {
            ull v = pk2(emb[(tn + k)*101 + e]);
            const ull* wr = (const ull*)&wsm[(e*KK + k)*FF];
            #pragma unroll
            for (int q = 0; q < 25; q++) ffma2(acc[q], wr[q], v);
        }
    }
    __syncthreads();
    float* part = sm;  // aliased scratch 3*96*50
    if (eq > 0) {
        float* p = part + (eq-1)*CVN*FF + tn*FF;
        #pragma unroll
        for (int q = 0; q < 25; q++) {
            p[2*q]   = lo32(acc[q]);
            p[2*q+1] = hi32(acc[q]);
        }
    }
    __syncthreads();
    if (eq == 0) {
        int n = base + tn;
        if (n < NN) {
            float* dst = &g_h[((size_t)b*NN + n)*HS];
            const float* p0 = part + tn*FF;
            const float* p1 = part + CVN*FF + tn*FF;
            const float* p2 = part + 2*CVN*FF + tn*FF;
            #pragma unroll
            for (int q = 0; q < 25; q++) {
                float a0 = lo32(acc[q]) + p0[2*q]   + p1[2*q]   + p2[2*q]   + convB[2*q];
                float a1 = hi32(acc[q]) + p0[2*q+1] + p1[2*q+1] + p2[2*q+1] + convB[2*q+1];
                dst[2*q]   = tanhf(a0);
                dst[2*q+1] = tanhf(a1);
            }
        }
    }
}

// ======================= Kernel 2: fused attention, TMA-staged, reg-tiled =======================
// grid (372, 8), 256 threads. tt = tid>>7 (y-group), tn = tid&127.
// Thread tile: 12 y-rows x 4 n-cols. Pass1: e=exp(U.h)->alpha, d. Pass2: a=e/d, logit += a*(F.h).
__global__ __launch_bounds__(256, 1)
void attn_kernel(const float* __restrict__ Uw, const float* __restrict__ finW,
                 const float* __restrict__ finB, const float* __restrict__ tgt,
                 float* __restrict__ yhat_out, float* __restrict__ alpha_out) {
    extern __shared__ float sm[];
    ull*   mbar = (ull*)sm;              // 2 mbarriers (16B)
    float* hbuf = sm + 4;                // 2*CHUNK_FLTS = 51200
    float* Us   = hbuf + 2*CHUNK_FLTS;   // 24*50
    float* Fs   = Us + ATY*FF;           // 24*50
    float* red  = Fs + ATY*FF;           // 8*12 = 96
    float* sinv = red + 96;              // 24

    int b = blockIdx.y, y0 = blockIdx.x*ATY, tid = threadIdx.x;
    int tt = tid >> 7, tn = tid & 127;
    int w = tid >> 5, lane = tid & 31;
    const float* hb = g_h + (size_t)b*NN*HS;
    uint32_t mb0 = s2u(&mbar[0]), mb1 = s2u(&mbar[1]);

    if (tid == 0) { mbar_init(mb0, 1); mbar_init(mb1, 1); }
    // stage U and F (clamped rows for y >= YY)
    for (int j = tid; j < ATY*FF; j += 256) {
        int r = j / FF, f = j - r*FF;
        int yy = y0 + r; if (yy >= YY) yy = YY-1;
        Us[j] = Uw[(size_t)yy*FF + f];
        Fs[j] = finW[(size_t)yy*FF + f];
    }
    __syncthreads();

    int phase[2] = {0, 0};
    // chunk byte sizes
    const uint32_t csz[NCHK] = {CN*HS*4, CN*HS*4, CN*HS*4, CN*HS*4, (NN-4*CN)*HS*4};

    // prefetch chunk 0 -> slot 0
    if (tid == 0) tma_bulk(s2u(hbuf), hb, csz[0], mb0);

    float d[TR];
    #pragma unroll
    for (int r = 0; r < TR; r++) d[r] = 0.f;

    // ---------------- Pass 1 ----------------
    for (int c = 0; c < NCHK; c++) {
        int slot = c & 1;
        if (c + 1 < NCHK && tid == 0)
            tma_bulk(s2u(hbuf + ((c+1)&1)*CHUNK_FLTS), hb + (size_t)(c+1)*CN*HS, csz[c+1], slot ? mb0 : mb1);
        mbar_wait(slot ? mb1 : mb0, phase[slot]); phase[slot] ^= 1;

        const float* hc = hbuf + slot*CHUNK_FLTS;
        ull acc[TR][TM];
        #pragma unroll
        for (int r = 0; r < TR; r++)
            #pragma unroll
            for (int j = 0; j < TM; j++) acc[r][j] = 0ull;

        #pragma unroll 5
        for (int fp = 0; fp < 25; fp++) {
            ull hv[TM];
            #pragma unroll
            for (int j = 0; j < TM; j++)
                hv[j] = *(const ull*)&hc[(tn + 128*j)*HS + 2*fp];
            ull uv[TR];
            #pragma unroll
            for (int r = 0; r < TR; r++)
                uv[r] = *(const ull*)&Us[(tt*TR + r)*FF + 2*fp];
            #pragma unroll
            for (int r = 0; r < TR; r++)
                #pragma unroll
                for (int j = 0; j < TM; j++) ffma2(acc[r][j], uv[r], hv[j]);
        }

        #pragma unroll
        for (int r = 0; r < TR; r++) {
            int y = y0 + tt*TR + r;
            bool vy = (y < YY);
            float* ao = alpha_out + (size_t)(b*YY + (vy ? y : 0))*NN;
            #pragma unroll
            for (int j = 0; j < TM; j++) {
                int n = c*CN + tn + 128*j;
                if (n < NN) {
                    float e = __expf(sum2(acc[r][j]));
                    d[r] += e;
                    if (vy) ao[n] = e;
                }
            }
        }
        __syncthreads();
    }

    // prefetch pass-2 chunk 0 -> slot NCHK&1 = 1
    if (tid == 0) tma_bulk(s2u(hbuf + (NCHK&1)*CHUNK_FLTS), hb, csz[0], (NCHK&1) ? mb1 : mb0);

    // ---- reduce d across the 128 tn-threads ----
    #pragma unroll
    for (int r = 0; r < TR; r++) {
        float v = d[r];
        #pragma unroll
        for (int o = 16; o; o >>= 1) v += __shfl_xor_sync(~0u, v, o);
        if (lane == 0) red[w*TR + r] = v;
    }
    __syncthreads();
    if (tid < ATY) {
        int g = tid / TR, r = tid - g*TR;
        float s = red[(g*4+0)*TR + r] + red[(g*4+1)*TR + r]
                + red[(g*4+2)*TR + r] + red[(g*4+3)*TR + r];
        sinv[tid] = 1.f / s;
    }
    __syncthreads();

    float inv[TR];
    #pragma unroll
    for (int r = 0; r < TR; r++) inv[r] = sinv[tt*TR + r];

    float lg[TR];
    #pragma unroll
    for (int r = 0; r < TR; r++) lg[r] = 0.f;

    // ---------------- Pass 2 ----------------
    for (int c = 0; c < NCHK; c++) {
        int slot = (NCHK + c) & 1;
        if (c + 1 < NCHK && tid == 0)
            tma_bulk(s2u(hbuf + ((NCHK+c+1)&1)*CHUNK_FLTS), hb + (size_t)(c+1)*CN*HS, csz[c+1],
                     ((NCHK+c+1)&1) ? mb1 : mb0);
        mbar_wait(slot ? mb1 : mb0, phase[slot]); phase[slot] ^= 1;

        const float* hc = hbuf + slot*CHUNK_FLTS;
        ull acc[TR][TM];
        #pragma unroll
        for (int r = 0; r < TR; r++)
            #pragma unroll
            for (int j = 0; j < TM; j++) acc[r][j] = 0ull;

        #pragma unroll 5
        for (int fp = 0; fp < 25; fp++) {
            ull hv[TM];
            #pragma unroll
            for (int j = 0; j < TM; j++)
                hv[j] = *(const ull*)&hc[(tn + 128*j)*HS + 2*fp];
            ull fv[TR];
            #pragma unroll
            for (int r = 0; r < TR; r++)
                fv[r] = *(const ull*)&Fs[(tt*TR + r)*FF + 2*fp];
            #pragma unroll
            for (int r = 0; r < TR; r++)
                #pragma unroll
                for (int j = 0; j < TM; j++) ffma2(acc[r][j], fv[r], hv[j]);
        }

        #pragma unroll
        for (int r = 0; r < TR; r++) {
            int y = y0 + tt*TR + r;
            bool vy = (y < YY);
            float* ao = alpha_out + (size_t)(b*YY + (vy ? y : 0))*NN;
            #pragma unroll
            for (int j = 0; j < TM; j++) {
                int n = c*CN + tn + 128*j;
                if (n < NN && vy) {
                    float a = ao[n] * inv[r];
                    ao[n] = a;
                    lg[r] += a * sum2(acc[r][j]);
                }
            }
        }
        __syncthreads();
    }

    // ---- reduce logits, epilogue ----
    #pragma unroll
    for (int r = 0; r < TR; r++) {
        float v = lg[r];
        #pragma unroll
        for (int o = 16; o; o >>= 1) v += __shfl_xor_sync(~0u, v, o);
        if (lane == 0) red[w*TR + r] = v;
    }
    __syncthreads();
    if (tid < ATY) {
        int g = tid / TR, r = tid - g*TR;
        float v = red[(g*4+0)*TR + r] + red[(g*4+1)*TR + r]
                + red[(g*4+2)*TR + r] + red[(g*4+3)*TR + r];
        int y = y0 + tid;
        if (y < YY) {
            float logit = v + finB[y];
            float p = 1.f / (1.f + __expf(-logit));
            yhat_out[(size_t)b*YY + y] = p;
            float pc = fminf(fmaxf(p, 1e-7f), 1.f - 1e-7f);
            float t = tgt[(size_t)b*YY + y];
            g_loss[(size_t)b*YY + y] = -(t*logf(pc) + (1.f - t)*log1pf(-pc));
        }
    }
}

// ======================= Kernel 3: deterministic loss reduction =======================
__global__ void loss_kernel(float* __restrict__ out) {
    __shared__ float r[1024];
    int tid = threadIdx.x;
    float a = 0.f;
    for (int i = tid; i < BY; i += 1024) a += g_loss[i];
    r[tid] = a;
    __syncthreads();
    for (int st = 512; st > 0; st >>= 1) {
        if (tid < st) r[tid] += r[tid + st];
        __syncthreads();
    }
    if (tid == 0) out[BY] = r[0] / (float)BY;
}

// ======================= Launch =======================
extern "C" void kernel_launch(void* const* d_in, const int* in_sizes, int n_in,
                              void* d_out, int out_size) {
    const int*   x      = (const int*)d_in[0];
    const float* target = (const float*)d_in[1];
    const float* embW   = (const float*)d_in[2];
    const float* convW  = (const float*)d_in[3];
    const float* convB  = (const float*)d_in[4];
    const float* Uw     = (const float*)d_in[5];
    const float* finW   = (const float*)d_in[6];
    const float* finB   = (const float*)d_in[7];
    float* out = (float*)d_out;
    float* yhat  = out;            // [B,Y]
    float* alpha = out + BY + 1;   // [B,Y,N]; out[BY] = loss

    const int conv_smem = (104*101 + 45000)*4 + 104*4;                      // 222432
    const int attn_smem = (4 + 2*CHUNK_FLTS + 2*ATY*FF + 96 + 24)*4;        // 214896

    cudaFuncSetAttribute(conv_kernel, cudaFuncAttributeMaxDynamicSharedMemorySize, conv_smem);
    cudaFuncSetAttribute(attn_kernel, cudaFuncAttributeMaxDynamicSharedMemorySize, attn_smem);

    conv_kernel<<<dim3((NN + CVN - 1)/CVN, BB), 384, conv_smem>>>(x, embW, convW, convB);
    attn_kernel<<<dim3((YY + ATY - 1)/ATY, BB), 256, attn_smem>>>(Uw, finW, finB, target, yhat, alpha);
    loss_kernel<<<1, 1024>>>(out);
}

// round 7
// speedup vs baseline: 2.7157x; 1.2074x over previous
#include <cuda_runtime.h>
#include <math.h>
#include <stdint.h>

#define BB 8
#define NN 2500
#define EE 100
#define FF 50
#define YY 8922
#define KK 9
#define BY (BB*YY)

#define HS   50        // g_h row stride in floats (stride-50 LDS.64 is bank-conflict-free)
#define ATY  32        // y rows per attn CTA (4 groups x 8)
#define TR   8         // y rows per thread
#define TM   4         // n cols per thread
#define CN   512       // n rows per chunk
#define NCHK 5         // ceil(2500/512)
#define CHUNK_FLTS (CN*HS)   // 25600

typedef unsigned long long ull;

__device__ float g_h[BB*NN*HS];
__device__ float g_loss[BY];

__device__ __forceinline__ void ffma2(ull &d, ull a, ull b) {
    asm("fma.rn.f32x2 %0, %1, %2, %0;" : "+l"(d) : "l"(a), "l"(b));
}
__device__ __forceinline__ ull pk2(float v) {
    ull r; unsigned u = __float_as_uint(v);
    asm("mov.b64 %0, {%1, %2};" : "=l"(r) : "r"(u), "r"(u));
    return r;
}
__device__ __forceinline__ float lo32(ull v){ return __uint_as_float((unsigned)v); }
__device__ __forceinline__ float hi32(ull v){ return __uint_as_float((unsigned)(v>>32)); }
__device__ __forceinline__ float sum2(ull v){ return lo32(v) + hi32(v); }

__device__ __forceinline__ uint32_t s2u(const void* p) {
    return (uint32_t)__cvta_generic_to_shared(p);
}
__device__ __forceinline__ void mbar_init(uint32_t mbar, int cnt) {
    asm volatile("mbarrier.init.shared.b64 [%0], %1;" :: "r"(mbar), "r"(cnt) : "memory");
}
__device__ __forceinline__ void tma_bulk(uint32_t dst, const void* src, uint32_t bytes, uint32_t mbar) {
    asm volatile("mbarrier.arrive.expect_tx.shared.b64 _, [%0], %1;" :: "r"(mbar), "r"(bytes) : "memory");
    asm volatile("cp.async.bulk.shared::cta.global.mbarrier::complete_tx::bytes [%0], [%1], %2, [%3];"
                 :: "r"(dst), "l"(src), "r"(bytes), "r"(mbar) : "memory");
}
__device__ __forceinline__ void mbar_wait(uint32_t mbar, int parity) {
    uint32_t done;
    do {
        asm volatile("{\n\t.reg .pred p;\n\t"
                     "mbarrier.try_wait.parity.acquire.cta.shared::cta.b64 p, [%1], %2, 0x989680;\n\t"
                     "selp.b32 %0, 1, 0, p;\n\t}"
                     : "=r"(done) : "r"(mbar), "r"((uint32_t)parity) : "memory");
    } while (!done);
}

// ======================= Kernel 1: embed + conv1d(K=9,SAME) + tanh =======================
#define CVN 96
__global__ __launch_bounds__(384, 1)
void conv_kernel(const int* __restrict__ x, const float* __restrict__ embW,
                 const float* __restrict__ convW, const float* __restrict__ convB) {
    extern __shared__ float sm[];
    float* emb = sm;                    // 104*101
    float* wsm = emb + 104*101;         // 900*50
    int*  toks = (int*)(wsm + 45000);

    int b = blockIdx.y, base = blockIdx.x * CVN, tid = threadIdx.x;

    if (tid < CVN + 8) {
        int n = base - 4 + tid;
        toks[tid] = (n >= 0 && n < NN) ? x[b*NN + n] : -1;
    }
    __syncthreads();
    for (int j = tid; j < FF*EE*KK; j += 384) {
        int f = j / 900, r = j - f*900;
        wsm[r*FF + f] = convW[j];
    }
    for (int j = tid; j < (CVN+8)*EE; j += 384) {
        int row = j / EE, c = j - row*EE;
        int tk = toks[row];
        emb[row*101 + c] = (tk >= 0) ? embW[(size_t)tk*EE + c] : 0.f;
    }
    __syncthreads();

    int tn = tid % CVN;
    int eq = tid / CVN;

    ull acc[25];
    #pragma unroll
    for (int q = 0; q < 25; q++) acc[q] = 0ull;

    for (int ee = 0; ee < 25; ee++) {
        int e = eq*25 + ee;
        #pragma unroll
        for (int k = 0; k < KK; k++) {
            ull v = pk2(emb[(tn + k)*101 + e]);
            const ull* wr = (const ull*)&wsm[(e*KK + k)*FF];
            #pragma unroll
            for (int q = 0; q < 25; q++) ffma2(acc[q], wr[q], v);
        }
    }
    __syncthreads();
    float* part = sm;  // aliased scratch 3*96*50
    if (eq > 0) {
        float* p = part + (eq-1)*CVN*FF + tn*FF;
        #pragma unroll
        for (int q = 0; q < 25; q++) {
            p[2*q]   = lo32(acc[q]);
            p[2*q+1] = hi32(acc[q]);
        }
    }
    __syncthreads();
    if (eq == 0) {
        int n = base + tn;
        if (n < NN) {
            float* dst = &g_h[((size_t)b*NN + n)*HS];
            const float* p0 = part + tn*FF;
            const float* p1 = part + CVN*FF + tn*FF;
            const float* p2 = part + 2*CVN*FF + tn*FF;
            #pragma unroll
            for (int q = 0; q < 25; q++) {
                float a0 = lo32(acc[q]) + p0[2*q]   + p1[2*q]   + p2[2*q]   + convB[2*q];
                float a1 = hi32(acc[q]) + p0[2*q+1] + p1[2*q+1] + p2[2*q+1] + convB[2*q+1];
                dst[2*q]   = tanhf(a0);
                dst[2*q+1] = tanhf(a1);
            }
        }
    }
}

// ======================= Kernel 2: fused attention, TMA-staged, reg-tiled =======================
// grid (279, 8), 512 threads (16 warps). tt = tid>>7 (4 y-groups of TR=8), tn = tid&127.
// Pass1: e=exp(U.h)->alpha, d. Pass2: a=e/d, logit += a*(F.h).
__global__ __launch_bounds__(512, 1)
void attn_kernel(const float* __restrict__ Uw, const float* __restrict__ finW,
                 const float* __restrict__ finB, const float* __restrict__ tgt,
                 float* __restrict__ yhat_out, float* __restrict__ alpha_out) {
    extern __shared__ float sm[];
    ull*   mbar = (ull*)sm;              // 2 mbarriers (16B)
    float* hbuf = sm + 4;                // 2*CHUNK_FLTS = 51200
    float* Us   = hbuf + 2*CHUNK_FLTS;   // ATY*50 = 1600
    float* Fs   = Us + ATY*FF;           // 1600
    float* red  = Fs + ATY*FF;           // 16 warps * TR = 128
    float* sinv = red + 128;             // 32

    int b = blockIdx.y, y0 = blockIdx.x*ATY, tid = threadIdx.x;
    int tt = tid >> 7, tn = tid & 127;
    int w = tid >> 5, lane = tid & 31;
    const float* hb = g_h + (size_t)b*NN*HS;
    uint32_t mb0 = s2u(&mbar[0]), mb1 = s2u(&mbar[1]);

    if (tid == 0) { mbar_init(mb0, 1); mbar_init(mb1, 1); }
    // stage U and F (clamped rows for y >= YY)
    for (int j = tid; j < ATY*FF; j += 512) {
        int r = j / FF, f = j - r*FF;
        int yy = y0 + r; if (yy >= YY) yy = YY-1;
        Us[j] = Uw[(size_t)yy*FF + f];
        Fs[j] = finW[(size_t)yy*FF + f];
    }
    __syncthreads();

    int phase[2] = {0, 0};
    const uint32_t csz[NCHK] = {CN*HS*4, CN*HS*4, CN*HS*4, CN*HS*4, (NN-4*CN)*HS*4};

    // prefetch chunk 0 -> slot 0
    if (tid == 0) tma_bulk(s2u(hbuf), hb, csz[0], mb0);

    float d[TR];
    #pragma unroll
    for (int r = 0; r < TR; r++) d[r] = 0.f;

    // ---------------- Pass 1 ----------------
    for (int c = 0; c < NCHK; c++) {
        int slot = c & 1;
        if (c + 1 < NCHK && tid == 0)
            tma_bulk(s2u(hbuf + ((c+1)&1)*CHUNK_FLTS), hb + (size_t)(c+1)*CN*HS, csz[c+1], slot ? mb0 : mb1);
        mbar_wait(slot ? mb1 : mb0, phase[slot]); phase[slot] ^= 1;

        const float* hc = hbuf + slot*CHUNK_FLTS;
        ull acc[TR][TM];
        #pragma unroll
        for (int r = 0; r < TR; r++)
            #pragma unroll
            for (int j = 0; j < TM; j++) acc[r][j] = 0ull;

        #pragma unroll 5
        for (int fp = 0; fp < 25; fp++) {
            ull hv[TM];
            #pragma unroll
            for (int j = 0; j < TM; j++)
                hv[j] = *(const ull*)&hc[(tn + 128*j)*HS + 2*fp];
            ull uv[TR];
            #pragma unroll
            for (int r = 0; r < TR; r++)
                uv[r] = *(const ull*)&Us[(tt*TR + r)*FF + 2*fp];
            #pragma unroll
            for (int r = 0; r < TR; r++)
                #pragma unroll
                for (int j = 0; j < TM; j++) ffma2(acc[r][j], uv[r], hv[j]);
        }

        #pragma unroll
        for (int r = 0; r < TR; r++) {
            int y = y0 + tt*TR + r;
            bool vy = (y < YY);
            float* ao = alpha_out + (size_t)(b*YY + (vy ? y : 0))*NN;
            #pragma unroll
            for (int j = 0; j < TM; j++) {
                int n = c*CN + tn + 128*j;
                if (n < NN) {
                    float e = __expf(sum2(acc[r][j]));
                    d[r] += e;
                    if (vy) ao[n] = e;
                }
            }
        }
        __syncthreads();
    }

    // prefetch pass-2 chunk 0 -> slot NCHK&1 = 1
    if (tid == 0) tma_bulk(s2u(hbuf + (NCHK&1)*CHUNK_FLTS), hb, csz[0], (NCHK&1) ? mb1 : mb0);

    // ---- reduce d across the 128 tn-threads (4 warps per y-group) ----
    #pragma unroll
    for (int r = 0; r < TR; r++) {
        float v = d[r];
        #pragma unroll
        for (int o = 16; o; o >>= 1) v += __shfl_xor_sync(~0u, v, o);
        if (lane == 0) red[w*TR + r] = v;
    }
    __syncthreads();
    if (tid < ATY) {
        int g = tid / TR, r = tid - g*TR;
        float s = red[(g*4+0)*TR + r] + red[(g*4+1)*TR + r]
                + red[(g*4+2)*TR + r] + red[(g*4+3)*TR + r];
        sinv[tid] = 1.f / s;
    }
    __syncthreads();

    float inv[TR];
    #pragma unroll
    for (int r = 0; r < TR; r++) inv[r] = sinv[tt*TR + r];

    float lg[TR];
    #pragma unroll
    for (int r = 0; r < TR; r++) lg[r] = 0.f;

    // ---------------- Pass 2 ----------------
    for (int c = 0; c < NCHK; c++) {
        int slot = (NCHK + c) & 1;
        if (c + 1 < NCHK && tid == 0)
            tma_bulk(s2u(hbuf + ((NCHK+c+1)&1)*CHUNK_FLTS), hb + (size_t)(c+1)*CN*HS, csz[c+1],
                     ((NCHK+c+1)&1) ? mb1 : mb0);
        mbar_wait(slot ? mb1 : mb0, phase[slot]); phase[slot] ^= 1;

        const float* hc = hbuf + slot*CHUNK_FLTS;
        ull acc[TR][TM];
        #pragma unroll
        for (int r = 0; r < TR; r++)
            #pragma unroll
            for (int j = 0; j < TM; j++) acc[r][j] = 0ull;

        #pragma unroll 5
        for (int fp = 0; fp < 25; fp++) {
            ull hv[TM];
            #pragma unroll
            for (int j = 0; j < TM; j++)
                hv[j] = *(const ull*)&hc[(tn + 128*j)*HS + 2*fp];
            ull fv[TR];
            #pragma unroll
            for (int r = 0; r < TR; r++)
                fv[r] = *(const ull*)&Fs[(tt*TR + r)*FF + 2*fp];
            #pragma unroll
            for (int r = 0; r < TR; r++)
                #pragma unroll
                for (int j = 0; j < TM; j++) ffma2(acc[r][j], fv[r], hv[j]);
        }

        #pragma unroll
        for (int r = 0; r < TR; r++) {
            int y = y0 + tt*TR + r;
            bool vy = (y < YY);
            float* ao = alpha_out + (size_t)(b*YY + (vy ? y : 0))*NN;
            #pragma unroll
            for (int j = 0; j < TM; j++) {
                int n = c*CN + tn + 128*j;
                if (n < NN && vy) {
                    float a = ao[n] * inv[r];
                    ao[n] = a;
                    lg[r] += a * sum2(acc[r][j]);
                }
            }
        }
        __syncthreads();
    }

    // ---- reduce logits, epilogue ----
    #pragma unroll
    for (int r = 0; r < TR; r++) {
        float v = lg[r];
        #pragma unroll
        for (int o = 16; o; o >>= 1) v += __shfl_xor_sync(~0u, v, o);
        if (lane == 0) red[w*TR + r] = v;
    }
    __syncthreads();
    if (tid < ATY) {
        int g = tid / TR, r = tid - g*TR;
        float v = red[(g*4+0)*TR + r] + red[(g*4+1)*TR + r]
                + red[(g*4+2)*TR + r] + red[(g*4+3)*TR + r];
        int y = y0 + tid;
        if (y < YY) {
            float logit = v + finB[y];
            float p = 1.f / (1.f + __expf(-logit));
            yhat_out[(size_t)b*YY + y] = p;
            float pc = fminf(fmaxf(p, 1e-7f), 1.f - 1e-7f);
            float t = tgt[(size_t)b*YY + y];
            g_loss[(size_t)b*YY + y] = -(t*logf(pc) + (1.f - t)*log1pf(-pc));
        }
    }
}

// ======================= Kernel 3: deterministic loss reduction =======================
__global__ void loss_kernel(float* __restrict__ out) {
    __shared__ float r[1024];
    int tid = threadIdx.x;
    float a = 0.f;
    for (int i = tid; i < BY; i += 1024) a += g_loss[i];
    r[tid] = a;
    __syncthreads();
    for (int st = 512; st > 0; st >>= 1) {
        if (tid < st) r[tid] += r[tid + st];
        __syncthreads();
    }
    if (tid == 0) out[BY] = r[0] / (float)BY;
}

// ======================= Launch =======================
extern "C" void kernel_launch(void* const* d_in, const int* in_sizes, int n_in,
                              void* d_out, int out_size) {
    const int*   x      = (const int*)d_in[0];
    const float* target = (const float*)d_in[1];
    const float* embW   = (const float*)d_in[2];
    const float* convW  = (const float*)d_in[3];
    const float* convB  = (const float*)d_in[4];
    const float* Uw     = (const float*)d_in[5];
    const float* finW   = (const float*)d_in[6];
    const float* finB   = (const float*)d_in[7];
    float* out = (float*)d_out;
    float* yhat  = out;            // [B,Y]
    float* alpha = out + BY + 1;   // [B,Y,N]; out[BY] = loss

    const int conv_smem = (104*101 + 45000)*4 + 104*4;                      // 222432
    const int attn_smem = (4 + 2*CHUNK_FLTS + 2*ATY*FF + 128 + 32)*4;       // 218272

    cudaFuncSetAttribute(conv_kernel, cudaFuncAttributeMaxDynamicSharedMemorySize, conv_smem);
    cudaFuncSetAttribute(attn_kernel, cudaFuncAttributeMaxDynamicSharedMemorySize, attn_smem);

    conv_kernel<<<dim3((NN + CVN - 1)/CVN, BB), 384, conv_smem>>>(x, embW, convW, convB);
    attn_kernel<<<dim3((YY + ATY - 1)/ATY, BB), 512, attn_smem>>>(Uw, finW, finB, target, yhat, alpha);
    loss_kernel<<<1, 1024>>>(out);
}